// round 15
// baseline (speedup 1.0000x reference)
#include <cuda_runtime.h>
#include <cstdint>
#include <cstddef>

#define T_STEPS 2048
#define N_ENV   256
#define HID     128
#define G3      384          // 3*HID
#define IDIM    128
#define M_TOTAL (T_STEPS*N_ENV)   // 524288
#define LDA     132          // padded smem row (floats)
#define RING    4            // gi ring depth (steps)

// Scratch for gi = x @ w_ih^T + b_ih : [M_TOTAL, G3] fp32 (805 MB)
__device__ float g_gi[(size_t)M_TOTAL * G3];

// ---------------------------------------------------------------------------
// helpers
// ---------------------------------------------------------------------------
__device__ __forceinline__ unsigned f2tf(float f){
  unsigned u; asm("cvt.rna.tf32.f32 %0, %1;" : "=r"(u) : "f"(f)); return u;
}
__device__ __forceinline__ void mma8(float* c, const unsigned* a, const unsigned* b){
  asm volatile("mma.sync.aligned.m16n8k8.row.col.f32.tf32.tf32.f32 "
      "{%0,%1,%2,%3}, {%4,%5,%6,%7}, {%8,%9}, {%0,%1,%2,%3};"
      : "+f"(c[0]), "+f"(c[1]), "+f"(c[2]), "+f"(c[3])
      : "r"(a[0]), "r"(a[1]), "r"(a[2]), "r"(a[3]), "r"(b[0]), "r"(b[1]));
}
__device__ __forceinline__ void cp16(float* dst, const float* src){
  unsigned s = (unsigned)__cvta_generic_to_shared(dst);
  asm volatile("cp.async.cg.shared.global [%0], [%1], 16;" :: "r"(s), "l"(src));
}
__device__ __forceinline__ void cp8(float* dst, const float* src){
  unsigned s = (unsigned)__cvta_generic_to_shared(dst);
  asm volatile("cp.async.ca.shared.global [%0], [%1], 8;" :: "r"(s), "l"(src));
}
__device__ __forceinline__ unsigned long long pk2(float lo, float hi){
  unsigned long long r; asm("mov.b64 %0, {%1,%2};" : "=l"(r) : "f"(lo), "f"(hi)); return r;
}
__device__ __forceinline__ void fma2(unsigned long long& d, unsigned long long a, unsigned long long b){
  asm("fma.rn.f32x2 %0, %1, %2, %0;" : "+l"(d) : "l"(a), "l"(b));
}
__device__ __forceinline__ unsigned long long add2(unsigned long long a, unsigned long long b){
  unsigned long long r; asm("add.rn.f32x2 %0, %1, %2;" : "=l"(r) : "l"(a), "l"(b)); return r;
}
__device__ __forceinline__ float2 upk(unsigned long long v){
  float lo, hi; asm("mov.b64 {%0,%1}, %2;" : "=f"(lo), "=f"(hi) : "l"(v));
  return make_float2(lo, hi);
}
// fast gates: MUFU.TANH (validated R13/R14: rel_err unchanged at 3.177e-4)
__device__ __forceinline__ float tanha(float x){
  float y; asm("tanh.approx.f32 %0, %1;" : "=f"(y) : "f"(x)); return y;
}
__device__ __forceinline__ float siga(float x){
  return fmaf(0.5f, tanha(0.5f*x), 0.5f);
}

// ---------------------------------------------------------------------------
// K1: gi = x @ w_ih^T + b_ih   (tf32 mma.sync) — exact R5 version
// ---------------------------------------------------------------------------
__global__ void __launch_bounds__(256) k1_gi(const float* __restrict__ x,
                                             const float* __restrict__ w_ih,
                                             const float* __restrict__ b_ih){
  extern __shared__ float sm[];
  float* Bs   = sm;
  float* As   = sm + 128*LDA;
  float* bias = sm + 3*128*LDA;

  const int tid  = threadIdx.x;
  const int nb   = blockIdx.x;
  const int slab = blockIdx.y;
  const int gbase = nb * 128;

  for (int idx = tid; idx < 128*32; idx += 256){
    int r = idx >> 5, c4 = idx & 31;
    float4 v = reinterpret_cast<const float4*>(w_ih + (size_t)(gbase + r)*IDIM)[c4];
    float* d = Bs + r*LDA + c4*4;
    d[0] = __uint_as_float(f2tf(v.x));
    d[1] = __uint_as_float(f2tf(v.y));
    d[2] = __uint_as_float(f2tf(v.z));
    d[3] = __uint_as_float(f2tf(v.w));
  }
  if (tid < 128) bias[tid] = b_ih[gbase + tid];

  const int lane = tid & 31, wid = tid >> 5;
  const int wm = wid >> 1, wn = wid & 1;
  const int grp = lane >> 2, qid = lane & 3;

  {
    const float* srcb = x + (size_t)slab * 128 * IDIM;
    #pragma unroll
    for (int i = 0; i < 16; i++){
      int c = tid + 256*i;
      int r = c >> 5, c16 = c & 31;
      cp16(As + r*LDA + c16*4, srcb + (size_t)r*IDIM + c16*4);
    }
    asm volatile("cp.async.commit_group;");
  }

  for (int it = 0; it < 32; it++){
    const int buf = it & 1;
    if (it + 1 < 32){
      int mt = slab + (it+1)*128;
      const float* srcb = x + (size_t)mt * 128 * IDIM;
      float* dstb = As + ((it+1)&1)*128*LDA;
      #pragma unroll
      for (int i = 0; i < 16; i++){
        int c = tid + 256*i;
        int r = c >> 5, c16 = c & 31;
        cp16(dstb + r*LDA + c16*4, srcb + (size_t)r*IDIM + c16*4);
      }
      asm volatile("cp.async.commit_group;");
      asm volatile("cp.async.wait_group 1;");
    } else {
      asm volatile("cp.async.wait_group 0;");
    }
    __syncthreads();

    float c[2][8][4];
    #pragma unroll
    for (int am=0;am<2;am++)
      #pragma unroll
      for(int an=0;an<8;an++)
        #pragma unroll
        for(int k=0;k<4;k++) c[am][an][k]=0.f;

    const float* A = As + buf*128*LDA;
    for (int k0 = 0; k0 < 128; k0 += 8){
      unsigned af[2][4];
      #pragma unroll
      for (int am=0; am<2; am++){
        int r0 = wm*32 + am*16 + grp;
        af[am][0] = f2tf(A[r0*LDA + k0 + qid]);
        af[am][1] = f2tf(A[(r0+8)*LDA + k0 + qid]);
        af[am][2] = f2tf(A[r0*LDA + k0 + qid + 4]);
        af[am][3] = f2tf(A[(r0+8)*LDA + k0 + qid + 4]);
      }
      unsigned bf[8][2];
      #pragma unroll
      for (int an=0; an<8; an++){
        int nr = wn*64 + an*8 + grp;
        bf[an][0] = __float_as_uint(Bs[nr*LDA + k0 + qid]);
        bf[an][1] = __float_as_uint(Bs[nr*LDA + k0 + qid + 4]);
      }
      #pragma unroll
      for (int am=0; am<2; am++)
        #pragma unroll
        for (int an=0; an<8; an++)
          mma8(c[am][an], af[am], bf[an]);
    }
    __syncthreads();

    const int mrow = (slab + it*128) * 128;
    #pragma unroll
    for (int am=0; am<2; am++){
      int r0 = mrow + wm*32 + am*16 + grp;
      #pragma unroll
      for (int an=0; an<8; an++){
        int colL = wn*64 + an*8 + 2*qid;
        float b0 = bias[colL], b1 = bias[colL+1];
        float2 v0 = make_float2(c[am][an][0]+b0, c[am][an][1]+b1);
        float2 v1 = make_float2(c[am][an][2]+b0, c[am][an][3]+b1);
        *reinterpret_cast<float2*>(&g_gi[(size_t)r0*G3 + gbase + colL]) = v0;
        *reinterpret_cast<float2*>(&g_gi[(size_t)(r0+8)*G3 + gbase + colL]) = v1;
      }
    }
  }
}

// ---------------------------------------------------------------------------
// K2: persistent GRU scan — R14 champion + (a) gates spread across all 12
// warps (warps 0-7: 11 units, warps 8-11: 10 units, contiguous j per warp),
// (b) 8-accumulator matvec (shorter RAW tail). All else identical.
// ---------------------------------------------------------------------------
__device__ __forceinline__ void matvec_row(
    const unsigned long long* __restrict__ wq,
    const float* __restrict__ h_base, float* gh_dst)
{
  const ulonglong2* hp = reinterpret_cast<const ulonglong2*>(h_base);
  unsigned long long A0=0, A1=0, A2=0, A3=0, A4=0, A5=0, A6=0, A7=0;
  #pragma unroll
  for (int i = 0; i < 8; i++){
    ulonglong2 v0 = hp[2*i];
    fma2(A0, wq[4*i],   v0.x);
    fma2(A1, wq[4*i+1], v0.y);
    ulonglong2 v1 = hp[2*i+1];
    fma2(A2, wq[4*i+2], v1.x);
    fma2(A3, wq[4*i+3], v1.y);
  }
  #pragma unroll
  for (int i = 8; i < 16; i++){
    ulonglong2 v0 = hp[2*i];
    fma2(A4, wq[4*i],   v0.x);
    fma2(A5, wq[4*i+1], v0.y);
    ulonglong2 v1 = hp[2*i+1];
    fma2(A6, wq[4*i+2], v1.x);
    fma2(A7, wq[4*i+3], v1.y);
  }
  unsigned long long B0 = add2(A0, A4);
  unsigned long long B1 = add2(A1, A5);
  unsigned long long B2 = add2(A2, A6);
  unsigned long long B3 = add2(A3, A7);
  float2 f = upk(add2(add2(B0, B1), add2(B2, B3)));
  *gh_dst = f.x + f.y;
}

__global__ void __launch_bounds__(384, 1) k2_scan(
    const float* __restrict__ h0,
    const float* __restrict__ masks,
    const float* __restrict__ w_hh,
    const float* __restrict__ b_hh,
    float* __restrict__ outs,
    float* __restrict__ h_final)
{
  __shared__ __align__(16) float h_sm[2][HID];
  __shared__ float gh_sm[2][G3];
  __shared__ __align__(16) float gi_ring[RING][2][G3];   // [slot][env][row]
  __shared__ __align__(8)  float m_ring[RING][2];        // [slot][env]

  const int g    = threadIdx.x;
  const int wrp  = g >> 5;
  const int lane = g & 31;
  const int e0   = blockIdx.x * 2;

  // ---- balanced gate-unit mapping: 128 units over 12 warps ----
  // warps 0-7: 11 units (j = w*11 + lane), warps 8-11: 10 units
  const int gcnt = (wrp < 8) ? 11 : 10;
  const int gst  = (wrp < 8) ? wrp*11 : 88 + (wrp - 8)*10;
  const bool is_gate = (lane < gcnt);
  const int j = is_gate ? (gst + lane) : 0;

  // w_hh row g, packed f32x2 (128 regs)
  unsigned long long wq[64];
  {
    const float4* wr = reinterpret_cast<const float4*>(w_hh + (size_t)g * HID);
    #pragma unroll
    for (int i = 0; i < 32; i++){
      float4 v = wr[i];
      wq[2*i]   = pk2(v.x, v.y);
      wq[2*i+1] = pk2(v.z, v.w);
    }
  }
  float bgr=0.f, bgz=0.f, bgn=0.f;
  if (is_gate){ bgr = b_hh[j]; bgz = b_hh[128+j]; bgn = b_hh[256+j]; }

  if (g < 256) h_sm[g>>7][g & 127] = h0[(size_t)(e0 + (g>>7))*HID + (g & 127)];

  const size_t STRIDE     = (size_t)N_ENV*G3;
  const size_t OUT_STRIDE = (size_t)N_ENV*HID;

  // cp.async staging assignment: threads 0..191 move one float4 of gi;
  // thread 192 moves both masks (8 bytes). (unchanged from champion)
  const int  cpk   = g;
  const bool cp_gi = (cpk < 192);
  const int  cp_env = (cpk >= 96);
  const int  cp_off = (cpk - cp_env*96) * 4;
  const float* gi_src_base = g_gi + (size_t)(e0 + cp_env)*G3 + cp_off;
  const float* mk_src_base = masks + e0;

  // Prologue: stage steps 0 and 1 (two committed groups)
  #pragma unroll
  for (int pt = 0; pt < 2; pt++){
    if (cp_gi)      cp16(&gi_ring[pt][cp_env][cp_off], gi_src_base + (size_t)pt*STRIDE);
    else if (cpk == 192) cp8(&m_ring[pt][0], mk_src_base + (size_t)pt*N_ENV);
    asm volatile("cp.async.commit_group;");
  }
  __syncthreads();

  #pragma unroll 1
  for (int t = 0; t < T_STEPS; t++){
    // Stage step t+2 (slot (t+2)&3), then guarantee group t is complete.
    if (t + 2 < T_STEPS){
      const int sl = (t+2) & (RING-1);
      if (cp_gi)      cp16(&gi_ring[sl][cp_env][cp_off], gi_src_base + (size_t)(t+2)*STRIDE);
      else if (cpk == 192) cp8(&m_ring[sl][0], mk_src_base + (size_t)(t+2)*N_ENV);
    }
    asm volatile("cp.async.commit_group;");
    asm volatile("cp.async.wait_group 2;");

    // ===== Phase A(t): gates env1 (step t-1) || matvec env0 (step t) =======
    if (is_gate && t > 0){
      const int sl = (t-1) & (RING-1);
      float cm = m_ring[sl][1];
      float cr = gi_ring[sl][1][j];
      float cz = gi_ring[sl][1][128+j];
      float cn = gi_ring[sl][1][256+j];
      float sr = gh_sm[1][j], sz = gh_sm[1][128+j], sn = gh_sm[1][256+j];
      float hold = h_sm[1][j];
      float r = siga(cr + fmaf(cm, sr, bgr));
      float z = siga(cz + fmaf(cm, sz, bgz));
      float n = tanha(cn + r * fmaf(cm, sn, bgn));
      float hn = fmaf(z, fmaf(cm, hold, -n), n);
      h_sm[1][j] = hn;
      outs[(size_t)(t-1)*OUT_STRIDE + (size_t)(e0+1)*HID + j] = hn;
    }
    matvec_row(wq, h_sm[0], &gh_sm[0][g]);
    __syncthreads();

    // ===== Phase B(t): gates env0 (step t) || matvec env1 (step t) =========
    if (is_gate){
      const int sl = t & (RING-1);
      float cm = m_ring[sl][0];
      float cr = gi_ring[sl][0][j];
      float cz = gi_ring[sl][0][128+j];
      float cn = gi_ring[sl][0][256+j];
      float sr = gh_sm[0][j], sz = gh_sm[0][128+j], sn = gh_sm[0][256+j];
      float hold = h_sm[0][j];
      float r = siga(cr + fmaf(cm, sr, bgr));
      float z = siga(cz + fmaf(cm, sz, bgz));
      float n = tanha(cn + r * fmaf(cm, sn, bgn));
      float hn = fmaf(z, fmaf(cm, hold, -n), n);
      h_sm[0][j] = hn;
      outs[(size_t)t*OUT_STRIDE + (size_t)e0*HID + j] = hn;
      if (t == T_STEPS-1 && h_final != nullptr)
        h_final[(size_t)e0*HID + j] = hn;
    }
    matvec_row(wq, h_sm[1], &gh_sm[1][g]);
    __syncthreads();
  }

  // ===== Epilogue: gates env1, step T-1 (slot (T-1)&3 completed) ===========
  if (is_gate){
    const int sl = (T_STEPS-1) & (RING-1);
    float cm = m_ring[sl][1];
    float cr = gi_ring[sl][1][j];
    float cz = gi_ring[sl][1][128+j];
    float cn = gi_ring[sl][1][256+j];
    float sr = gh_sm[1][j], sz = gh_sm[1][128+j], sn = gh_sm[1][256+j];
    float hold = h_sm[1][j];
    float r = siga(cr + fmaf(cm, sr, bgr));
    float z = siga(cz + fmaf(cm, sz, bgz));
    float n = tanha(cn + r * fmaf(cm, sn, bgn));
    float hn = fmaf(z, fmaf(cm, hold, -n), n);
    outs[(size_t)(T_STEPS-1)*OUT_STRIDE + (size_t)(e0+1)*HID + j] = hn;
    if (h_final != nullptr) h_final[(size_t)(e0+1)*HID + j] = hn;
  }
}

// ---------------------------------------------------------------------------
extern "C" void kernel_launch(void* const* d_in, const int* in_sizes, int n_in,
                              void* d_out, int out_size){
  (void)in_sizes; (void)n_in;
  const float* x     = (const float*)d_in[0];
  const float* h0    = (const float*)d_in[1];
  const float* masks = (const float*)d_in[2];
  const float* w_ih  = (const float*)d_in[3];
  const float* w_hh  = (const float*)d_in[4];
  const float* b_ih  = (const float*)d_in[5];
  const float* b_hh  = (const float*)d_in[6];

  float* outs = (float*)d_out;
  float* hf = nullptr;
  if ((long long)out_size >= (long long)M_TOTAL*HID + (long long)N_ENV*HID)
    hf = outs + (size_t)M_TOTAL*HID;

  const int k1_smem = (3*128*LDA + 128) * (int)sizeof(float);
  cudaFuncSetAttribute(k1_gi, cudaFuncAttributeMaxDynamicSharedMemorySize, k1_smem);
  k1_gi<<<dim3(3,128), 256, k1_smem>>>(x, w_ih, b_ih);
  k2_scan<<<128, 384>>>(h0, masks, w_hh, b_hh, outs, hf);
}

// round 16
// speedup vs baseline: 1.1736x; 1.1736x over previous
#include <cuda_runtime.h>
#include <cuda_fp16.h>
#include <cstdint>
#include <cstddef>

#define T_STEPS 2048
#define N_ENV   256
#define HID     128
#define G3      384          // 3*HID
#define IDIM    128
#define M_TOTAL (T_STEPS*N_ENV)   // 524288
#define LDA     132          // padded smem row (floats)
#define BLDH    136          // Bs fp16 row stride (halves)
#define RING    4            // gi ring depth (steps)

// Scratch for gi = x @ w_ih^T + b_ih : [M_TOTAL, G3] fp32 (805 MB)
__device__ float g_gi[(size_t)M_TOTAL * G3];

// ---------------------------------------------------------------------------
// helpers
// ---------------------------------------------------------------------------
__device__ __forceinline__ void hmma16(float* c, const unsigned* a, unsigned b0, unsigned b1){
  asm volatile("mma.sync.aligned.m16n8k16.row.col.f32.f16.f16.f32 "
      "{%0,%1,%2,%3}, {%4,%5,%6,%7}, {%8,%9}, {%0,%1,%2,%3};"
      : "+f"(c[0]), "+f"(c[1]), "+f"(c[2]), "+f"(c[3])
      : "r"(a[0]), "r"(a[1]), "r"(a[2]), "r"(a[3]), "r"(b0), "r"(b1));
}
__device__ __forceinline__ void cp16(float* dst, const float* src){
  unsigned s = (unsigned)__cvta_generic_to_shared(dst);
  asm volatile("cp.async.cg.shared.global [%0], [%1], 16;" :: "r"(s), "l"(src));
}
__device__ __forceinline__ void cp8(float* dst, const float* src){
  unsigned s = (unsigned)__cvta_generic_to_shared(dst);
  asm volatile("cp.async.ca.shared.global [%0], [%1], 8;" :: "r"(s), "l"(src));
}
__device__ __forceinline__ unsigned pkh2(float a, float b){
  unsigned u;
  asm("cvt.rn.f16x2.f32 %0, %1, %2;" : "=r"(u) : "f"(b), "f"(a));
  return u;
}
__device__ __forceinline__ unsigned long long pk2(float lo, float hi){
  unsigned long long r; asm("mov.b64 %0, {%1,%2};" : "=l"(r) : "f"(lo), "f"(hi)); return r;
}
__device__ __forceinline__ void fma2(unsigned long long& d, unsigned long long a, unsigned long long b){
  asm("fma.rn.f32x2 %0, %1, %2, %0;" : "+l"(d) : "l"(a), "l"(b));
}
__device__ __forceinline__ float2 upk(unsigned long long v){
  float lo, hi; asm("mov.b64 {%0,%1}, %2;" : "=f"(lo), "=f"(hi) : "l"(v));
  return make_float2(lo, hi);
}
// fast gates: MUFU.TANH (validated R13/R14: rel_err unchanged at 3.177e-4)
__device__ __forceinline__ float tanha(float x){
  float y; asm("tanh.approx.f32 %0, %1;" : "=f"(y) : "f"(x)); return y;
}
__device__ __forceinline__ float siga(float x){
  return fmaf(0.5f, tanha(0.5f*x), 0.5f);
}

// ---------------------------------------------------------------------------
// K1: gi = x @ w_ih^T + b_ih   — fp16 m16n8k16 mma.sync (fp32 accumulate).
// fp16 mantissa == tf32 mantissa, so accuracy matches the old tf32 path;
// each MMA moves 2x the MACs -> ~2x tensor throughput on the legacy pipe.
// grid (3,128), block 256; CTA (nb, slab): n-block nb, m-tiles slab + 128*it.
// ---------------------------------------------------------------------------
__global__ void __launch_bounds__(256) k1_gi(const float* __restrict__ x,
                                             const float* __restrict__ w_ih,
                                             const float* __restrict__ b_ih){
  extern __shared__ __align__(16) char SM1[];
  __half* Bs   = (__half*)SM1;                           // [128][BLDH] fp16
  float*  As   = (float*)(SM1 + 128*BLDH*2);             // [2][128][LDA] fp32
  float*  bias = (float*)(SM1 + 128*BLDH*2 + 2*128*LDA*4);

  const int tid  = threadIdx.x;
  const int nb   = blockIdx.x;
  const int slab = blockIdx.y;
  const int gbase = nb * 128;

  // Load B block (w_ih rows gbase..gbase+127) as fp16
  for (int idx = tid; idx < 128*IDIM; idx += 256){
    int r = idx >> 7, c = idx & 127;
    Bs[r*BLDH + c] = __float2half_rn(w_ih[(size_t)(gbase + r)*IDIM + c]);
  }
  if (tid < 128) bias[tid] = b_ih[gbase + tid];

  const int lane = tid & 31, wid = tid >> 5;
  const int wm = wid >> 1, wn = wid & 1;
  const int grp = lane >> 2, qid = lane & 3;

  // prefetch A tile 0 into buf 0 (fp32, raw cp.async)
  {
    const float* srcb = x + (size_t)slab * 128 * IDIM;
    #pragma unroll
    for (int i = 0; i < 16; i++){
      int c = tid + 256*i;
      int r = c >> 5, c16 = c & 31;
      cp16(As + r*LDA + c16*4, srcb + (size_t)r*IDIM + c16*4);
    }
    asm volatile("cp.async.commit_group;");
  }

  for (int it = 0; it < 32; it++){
    const int buf = it & 1;
    if (it + 1 < 32){
      int mt = slab + (it+1)*128;
      const float* srcb = x + (size_t)mt * 128 * IDIM;
      float* dstb = As + ((it+1)&1)*128*LDA;
      #pragma unroll
      for (int i = 0; i < 16; i++){
        int c = tid + 256*i;
        int r = c >> 5, c16 = c & 31;
        cp16(dstb + r*LDA + c16*4, srcb + (size_t)r*IDIM + c16*4);
      }
      asm volatile("cp.async.commit_group;");
      asm volatile("cp.async.wait_group 1;");
    } else {
      asm volatile("cp.async.wait_group 0;");
    }
    __syncthreads();

    float c[2][8][4];
    #pragma unroll
    for (int am=0;am<2;am++)
      #pragma unroll
      for(int an=0;an<8;an++)
        #pragma unroll
        for(int k=0;k<4;k++) c[am][an][k]=0.f;

    const float* A = As + buf*128*LDA;
    #pragma unroll
    for (int kd = 0; kd < 8; kd++){
      const int k0 = kd*16 + qid*2;
      // A fragments (m16n8k16 row-major): pack fp32 pairs -> fp16x2
      unsigned af[2][4];
      #pragma unroll
      for (int am=0; am<2; am++){
        int r0 = wm*32 + am*16 + grp;
        float2 v00 = *reinterpret_cast<const float2*>(A + r0*LDA     + k0);
        float2 v01 = *reinterpret_cast<const float2*>(A + (r0+8)*LDA + k0);
        float2 v10 = *reinterpret_cast<const float2*>(A + r0*LDA     + k0 + 8);
        float2 v11 = *reinterpret_cast<const float2*>(A + (r0+8)*LDA + k0 + 8);
        af[am][0] = pkh2(v00.x, v00.y);
        af[am][1] = pkh2(v01.x, v01.y);
        af[am][2] = pkh2(v10.x, v10.y);
        af[am][3] = pkh2(v11.x, v11.y);
      }
      // B fragments (col-major): 2 packed halves per reg, contiguous in k
      unsigned bf[8][2];
      #pragma unroll
      for (int an=0; an<8; an++){
        int nr = wn*64 + an*8 + grp;
        bf[an][0] = *reinterpret_cast<const unsigned*>(Bs + nr*BLDH + k0);
        bf[an][1] = *reinterpret_cast<const unsigned*>(Bs + nr*BLDH + k0 + 8);
      }
      #pragma unroll
      for (int am=0; am<2; am++)
        #pragma unroll
        for (int an=0; an<8; an++)
          hmma16(c[am][an], af[am], bf[an][0], bf[an][1]);
    }
    __syncthreads();

    const int mrow = (slab + it*128) * 128;
    #pragma unroll
    for (int am=0; am<2; am++){
      int r0 = mrow + wm*32 + am*16 + grp;
      #pragma unroll
      for (int an=0; an<8; an++){
        int colL = wn*64 + an*8 + 2*qid;
        float b0 = bias[colL], b1 = bias[colL+1];
        float2 v0 = make_float2(c[am][an][0]+b0, c[am][an][1]+b1);
        float2 v1 = make_float2(c[am][an][2]+b0, c[am][an][3]+b1);
        *reinterpret_cast<float2*>(&g_gi[(size_t)r0*G3 + gbase + colL]) = v0;
        *reinterpret_cast<float2*>(&g_gi[(size_t)(r0+8)*G3 + gbase + colL]) = v1;
      }
    }
  }
}

// ---------------------------------------------------------------------------
// K2: persistent GRU scan — EXACT R14 champion (best k2 = 2067 us).
// 128 CTAs x 384 threads, 2 envs per CTA; cp.async gi/mask ring (2-step
// lookahead); gates on warps 0-3; tanh.approx gates.
// Phase A(t): matvec env0 step t (all)  || gates env1 step t-1 (warps 0-3)
// Phase B(t): matvec env1 step t (all)  || gates env0 step t   (warps 0-3)
// ---------------------------------------------------------------------------
__device__ __forceinline__ void matvec_row(
    const unsigned long long* __restrict__ wq,
    const float* __restrict__ h_base, float* gh_dst)
{
  const ulonglong2* hp = reinterpret_cast<const ulonglong2*>(h_base);
  unsigned long long A0=0, A1=0, A2=0, A3=0;
  #pragma unroll
  for (int i = 0; i < 16; i++){
    ulonglong2 v0 = hp[2*i];
    fma2(A0, wq[4*i],   v0.x);
    fma2(A1, wq[4*i+1], v0.y);
    ulonglong2 v1 = hp[2*i+1];
    fma2(A2, wq[4*i+2], v1.x);
    fma2(A3, wq[4*i+3], v1.y);
  }
  float2 f0=upk(A0), f1=upk(A1), f2=upk(A2), f3=upk(A3);
  *gh_dst = ((f0.x+f0.y)+(f1.x+f1.y)) + ((f2.x+f2.y)+(f3.x+f3.y));
}

__global__ void __launch_bounds__(384, 1) k2_scan(
    const float* __restrict__ h0,
    const float* __restrict__ masks,
    const float* __restrict__ w_hh,
    const float* __restrict__ b_hh,
    float* __restrict__ outs,
    float* __restrict__ h_final)
{
  __shared__ __align__(16) float h_sm[2][HID];
  __shared__ float gh_sm[2][G3];
  __shared__ __align__(16) float gi_ring[RING][2][G3];   // [slot][env][row]
  __shared__ __align__(8)  float m_ring[RING][2];        // [slot][env]

  const int g  = threadIdx.x;
  const int j  = g & 127;
  const bool is_gate = (g < 128);
  const int e0 = blockIdx.x * 2;

  // w_hh row g, packed f32x2 (128 regs)
  unsigned long long wq[64];
  {
    const float4* wr = reinterpret_cast<const float4*>(w_hh + (size_t)g * HID);
    #pragma unroll
    for (int i = 0; i < 32; i++){
      float4 v = wr[i];
      wq[2*i]   = pk2(v.x, v.y);
      wq[2*i+1] = pk2(v.z, v.w);
    }
  }
  float bgr=0.f, bgz=0.f, bgn=0.f;
  if (is_gate){ bgr = b_hh[j]; bgz = b_hh[128+j]; bgn = b_hh[256+j]; }

  if (g < 256) h_sm[g>>7][j] = h0[(size_t)(e0 + (g>>7))*HID + j];

  const size_t STRIDE     = (size_t)N_ENV*G3;
  const size_t OUT_STRIDE = (size_t)N_ENV*HID;

  // cp.async staging assignment: threads 0..191 move one float4 of gi;
  // thread 192 moves both masks (8 bytes).
  const int  cpk   = g;
  const bool cp_gi = (cpk < 192);
  const int  cp_env = (cpk >= 96);
  const int  cp_off = (cpk - cp_env*96) * 4;
  const float* gi_src_base = g_gi + (size_t)(e0 + cp_env)*G3 + cp_off;
  const float* mk_src_base = masks + e0;

  // Prologue: stage steps 0 and 1 (two committed groups)
  #pragma unroll
  for (int pt = 0; pt < 2; pt++){
    if (cp_gi)      cp16(&gi_ring[pt][cp_env][cp_off], gi_src_base + (size_t)pt*STRIDE);
    else if (cpk == 192) cp8(&m_ring[pt][0], mk_src_base + (size_t)pt*N_ENV);
    asm volatile("cp.async.commit_group;");
  }
  __syncthreads();

  #pragma unroll 1
  for (int t = 0; t < T_STEPS; t++){
    // Stage step t+2 (slot (t+2)&3), then guarantee group t is complete.
    if (t + 2 < T_STEPS){
      const int sl = (t+2) & (RING-1);
      if (cp_gi)      cp16(&gi_ring[sl][cp_env][cp_off], gi_src_base + (size_t)(t+2)*STRIDE);
      else if (cpk == 192) cp8(&m_ring[sl][0], mk_src_base + (size_t)(t+2)*N_ENV);
    }
    asm volatile("cp.async.commit_group;");
    asm volatile("cp.async.wait_group 2;");   // group t done (visible after phase-A barrier)

    // ===== Phase A(t): gates env1 (step t-1) || matvec env0 (step t) =======
    if (is_gate && t > 0){
      const int sl = (t-1) & (RING-1);
      float cm = m_ring[sl][1];
      float cr = gi_ring[sl][1][j];
      float cz = gi_ring[sl][1][128+j];
      float cn = gi_ring[sl][1][256+j];
      float sr = gh_sm[1][j], sz = gh_sm[1][128+j], sn = gh_sm[1][256+j];
      float hold = h_sm[1][j];
      float r = siga(cr + fmaf(cm, sr, bgr));
      float z = siga(cz + fmaf(cm, sz, bgz));
      float n = tanha(cn + r * fmaf(cm, sn, bgn));
      float hn = fmaf(z, fmaf(cm, hold, -n), n);
      h_sm[1][j] = hn;
      outs[(size_t)(t-1)*OUT_STRIDE + (size_t)(e0+1)*HID + j] = hn;
    }
    matvec_row(wq, h_sm[0], &gh_sm[0][g]);
    __syncthreads();

    // ===== Phase B(t): gates env0 (step t) || matvec env1 (step t) =========
    if (is_gate){
      const int sl = t & (RING-1);
      float cm = m_ring[sl][0];
      float cr = gi_ring[sl][0][j];
      float cz = gi_ring[sl][0][128+j];
      float cn = gi_ring[sl][0][256+j];
      float sr = gh_sm[0][j], sz = gh_sm[0][128+j], sn = gh_sm[0][256+j];
      float hold = h_sm[0][j];
      float r = siga(cr + fmaf(cm, sr, bgr));
      float z = siga(cz + fmaf(cm, sz, bgz));
      float n = tanha(cn + r * fmaf(cm, sn, bgn));
      float hn = fmaf(z, fmaf(cm, hold, -n), n);
      h_sm[0][j] = hn;
      outs[(size_t)t*OUT_STRIDE + (size_t)e0*HID + j] = hn;
      if (t == T_STEPS-1 && h_final != nullptr)
        h_final[(size_t)e0*HID + j] = hn;
    }
    matvec_row(wq, h_sm[1], &gh_sm[1][g]);
    __syncthreads();
  }

  // ===== Epilogue: gates env1, step T-1 (slot (T-1)&3 completed) ===========
  if (is_gate){
    const int sl = (T_STEPS-1) & (RING-1);
    float cm = m_ring[sl][1];
    float cr = gi_ring[sl][1][j];
    float cz = gi_ring[sl][1][128+j];
    float cn = gi_ring[sl][1][256+j];
    float sr = gh_sm[1][j], sz = gh_sm[1][128+j], sn = gh_sm[1][256+j];
    float hold = h_sm[1][j];
    float r = siga(cr + fmaf(cm, sr, bgr));
    float z = siga(cz + fmaf(cm, sz, bgz));
    float n = tanha(cn + r * fmaf(cm, sn, bgn));
    float hn = fmaf(z, fmaf(cm, hold, -n), n);
    outs[(size_t)(T_STEPS-1)*OUT_STRIDE + (size_t)(e0+1)*HID + j] = hn;
    if (h_final != nullptr) h_final[(size_t)(e0+1)*HID + j] = hn;
  }
}

// ---------------------------------------------------------------------------
extern "C" void kernel_launch(void* const* d_in, const int* in_sizes, int n_in,
                              void* d_out, int out_size){
  (void)in_sizes; (void)n_in;
  const float* x     = (const float*)d_in[0];
  const float* h0    = (const float*)d_in[1];
  const float* masks = (const float*)d_in[2];
  const float* w_ih  = (const float*)d_in[3];
  const float* w_hh  = (const float*)d_in[4];
  const float* b_ih  = (const float*)d_in[5];
  const float* b_hh  = (const float*)d_in[6];

  float* outs = (float*)d_out;
  float* hf = nullptr;
  if ((long long)out_size >= (long long)M_TOTAL*HID + (long long)N_ENV*HID)
    hf = outs + (size_t)M_TOTAL*HID;

  const int k1_smem = 128*BLDH*2 + 2*128*LDA*4 + 128*4;
  cudaFuncSetAttribute(k1_gi, cudaFuncAttributeMaxDynamicSharedMemorySize, k1_smem);
  k1_gi<<<dim3(3,128), 256, k1_smem>>>(x, w_ih, b_ih);
  k2_scan<<<128, 384>>>(h0, masks, w_hh, b_hh, outs, hf);
}